// round 3
// baseline (speedup 1.0000x reference)
#include <cuda_runtime.h>

#define TT 35
#define CC 4
#define CIN 7
#define HH 64
#define BN_EPS 1e-5

// stats: 28 upper-tri entries of M = sum(aug aug^T) followed by 7 entries of S1 = sum(aug)
__device__ float g_stats[35];
__device__ float g_Wp[HH * CIN];
__device__ float g_bp[HH];

__global__ void zero_stats_kernel() {
    if (threadIdx.x < 35) g_stats[threadIdx.x] = 0.f;
}

__device__ __forceinline__ void accum_row(float* acc, float4 r, float mx, float my, float mz) {
    float a[7];
    a[0] = r.x; a[1] = r.y; a[2] = r.z; a[3] = r.w;
    a[4] = r.x - mx; a[5] = r.y - my; a[6] = r.z - mz;
    int idx = 0;
#pragma unroll
    for (int k = 0; k < 7; k++) {
#pragma unroll
        for (int l = 0; l <= k; l++) {
            acc[idx] = fmaf(a[k], a[l], acc[idx]);
            idx++;
        }
    }
#pragma unroll
    for (int k = 0; k < 7; k++) acc[28 + k] += a[k];
}

// One warp processes voxels in a grid-stride chain; accumulates the 35 moment
// scalars per-lane, warp-reduces, block-combines in smem, then one atomic set
// per block into g_stats.
__global__ void stats_kernel(const float* __restrict__ vox, int N) {
    const unsigned FULL = 0xffffffffu;
    int lane = threadIdx.x & 31;
    int warpId = (blockIdx.x * blockDim.x + threadIdx.x) >> 5;
    int nWarps = (gridDim.x * blockDim.x) >> 5;

    __shared__ float bacc[35];
    if (threadIdx.x < 35) bacc[threadIdx.x] = 0.f;
    __syncthreads();

    float acc[35];
#pragma unroll
    for (int i = 0; i < 35; i++) acc[i] = 0.f;

    for (int n = warpId; n < N; n += nWarps) {
        const float4* vp = (const float4*)(vox + (size_t)n * (TT * CC));
        float4 r0 = vp[lane];                       // rows 0..31
        float4 r1 = make_float4(0.f, 0.f, 0.f, 0.f);
        bool has2 = (lane < (TT - 32));             // lanes 0..2 also take rows 32..34
        if (has2) r1 = vp[lane + 32];

        // per-channel sums (only ch 0..2 needed for the mean) + nonempty count
        float sx = r0.x + r1.x;
        float sy = r0.y + r1.y;
        float sz = r0.z + r1.z;
        float rs0 = r0.x + r0.y + r0.z + r0.w;
        float cnt = (rs0 != 0.f) ? 1.f : 0.f;
        if (has2) {
            float rs1 = r1.x + r1.y + r1.z + r1.w;
            if (rs1 != 0.f) cnt += 1.f;
        }
#pragma unroll
        for (int o = 16; o; o >>= 1) {
            sx  += __shfl_down_sync(FULL, sx, o);
            sy  += __shfl_down_sync(FULL, sy, o);
            sz  += __shfl_down_sync(FULL, sz, o);
            cnt += __shfl_down_sync(FULL, cnt, o);
        }
        sx  = __shfl_sync(FULL, sx, 0);
        sy  = __shfl_sync(FULL, sy, 0);
        sz  = __shfl_sync(FULL, sz, 0);
        cnt = __shfl_sync(FULL, cnt, 0);

        float inv = 1.f / cnt;
        float mx = sx * inv, my = sy * inv, mz = sz * inv;

        accum_row(acc, r0, mx, my, mz);
        if (has2) accum_row(acc, r1, mx, my, mz);
    }

#pragma unroll
    for (int i = 0; i < 35; i++) {
        float v = acc[i];
#pragma unroll
        for (int o = 16; o; o >>= 1) v += __shfl_down_sync(FULL, v, o);
        if (lane == 0) atomicAdd(&bacc[i], v);
    }
    __syncthreads();
    if (threadIdx.x < 35) atomicAdd(&g_stats[threadIdx.x], bacc[threadIdx.x]);
}

// Fold BN (batch stats from moments) into the linear layer. fp64 to avoid any
// cancellation in var = E[x^2] - mu^2.
__global__ void finalize_kernel(const float* __restrict__ Wm, const float* __restrict__ b,
                                const float* __restrict__ gamma, const float* __restrict__ beta,
                                int N) {
    int j = threadIdx.x;
    if (j >= HH) return;
    double M[28], S1[7];
#pragma unroll
    for (int i = 0; i < 28; i++) M[i] = (double)g_stats[i];
#pragma unroll
    for (int k = 0; k < 7; k++) S1[k] = (double)g_stats[28 + k];

    double w[7];
#pragma unroll
    for (int k = 0; k < 7; k++) w[k] = (double)Wm[j * CIN + k];
    double bj = (double)b[j];

    double dotWS = 0.0;
#pragma unroll
    for (int k = 0; k < 7; k++) dotWS += w[k] * S1[k];

    double quad = 0.0;
    int idx = 0;
#pragma unroll
    for (int k = 0; k < 7; k++) {
#pragma unroll
        for (int l = 0; l <= k; l++) {
            double term = w[k] * w[l] * M[idx];
            quad += (l == k) ? term : 2.0 * term;
            idx++;
        }
    }

    double Nt = (double)N * (double)TT;
    double sumx  = dotWS + Nt * bj;
    double sumxx = quad + 2.0 * bj * dotWS + Nt * bj * bj;
    double mu  = sumx / Nt;
    double var = sumxx / Nt - mu * mu;
    double inv = 1.0 / sqrt(var + (double)BN_EPS);
    double a = (double)gamma[j] * inv;

#pragma unroll
    for (int k = 0; k < 7; k++) g_Wp[j * CIN + k] = (float)(a * w[k]);
    g_bp[j] = (float)((double)beta[j] + a * (bj - mu));
}

// One 64-thread block per voxel. Thread j owns output channel j: computes
// x[t][j] for all t with the BN-folded weights, tracks the per-channel max,
// stages x in smem, then both warps stream the [35 x 128] output tile with
// float4 stores.
__global__ __launch_bounds__(64) void main_kernel(const float* __restrict__ vox,
                                                  float* __restrict__ out) {
    __shared__ float srow[TT * CC];     // voxel rows
    __shared__ float smean[3];
    __shared__ float scnt;
    __shared__ float swp[HH * CIN];
    __shared__ float xbuf[TT * HH];
    __shared__ float maxbuf[HH];

    int n = blockIdx.x;
    int j = threadIdx.x;

    // stage folded weights (coalesced)
#pragma unroll
    for (int k = 0; k < 7; k++) swp[j + k * HH] = g_Wp[j + k * HH];
    float bp = g_bp[j];

    if (j < TT) ((float4*)srow)[j] = ((const float4*)(vox + (size_t)n * (TT * CC)))[j];
    __syncthreads();

    if (j < 3) {
        float s = 0.f;
        for (int t = 0; t < TT; t++) s += srow[t * CC + j];
        smean[j] = s;
    } else if (j == 3) {
        float c = 0.f;
        for (int t = 0; t < TT; t++) {
            float rs = srow[t * CC] + srow[t * CC + 1] + srow[t * CC + 2] + srow[t * CC + 3];
            if (rs != 0.f) c += 1.f;
        }
        scnt = c;
    }
    __syncthreads();

    float icnt = 1.f / scnt;
    float mx = smean[0] * icnt, my = smean[1] * icnt, mz = smean[2] * icnt;

    float w0 = swp[j * CIN + 0], w1 = swp[j * CIN + 1], w2 = swp[j * CIN + 2],
          w3 = swp[j * CIN + 3], w4 = swp[j * CIN + 4], w5 = swp[j * CIN + 5],
          w6 = swp[j * CIN + 6];

    float maxv = 0.f;  // ReLU outputs are >= 0, so 0 is the identity for this max
#pragma unroll 5
    for (int t = 0; t < TT; t++) {
        float x = srow[t * CC], y = srow[t * CC + 1], z = srow[t * CC + 2], w = srow[t * CC + 3];
        float v = bp;
        v = fmaf(w0, x, v);
        v = fmaf(w1, y, v);
        v = fmaf(w2, z, v);
        v = fmaf(w3, w, v);
        v = fmaf(w4, x - mx, v);
        v = fmaf(w5, y - my, v);
        v = fmaf(w6, z - mz, v);
        v = fmaxf(v, 0.f);
        xbuf[t * HH + j] = v;
        maxv = fmaxf(maxv, v);
    }
    maxbuf[j] = maxv;
    __syncthreads();

    // write [TT x 128]: first 64 channels = x, next 64 = broadcast max
    float4* op = (float4*)(out + (size_t)n * (TT * 2 * HH));
    const int NV4 = TT * 2 * HH / 4;  // 1120
    for (int p = j; p < NV4; p += HH) {
        int e = p * 4;
        int t = e >> 7;          // /128
        int c = e & 127;
        float4 val;
        if (c < HH) val = *(const float4*)&xbuf[t * HH + c];
        else        val = *(const float4*)&maxbuf[c - HH];
        op[p] = val;
    }
}

extern "C" void kernel_launch(void* const* d_in, const int* in_sizes, int n_in,
                              void* d_out, int out_size) {
    const float* vox   = (const float*)d_in[0];
    const float* Wm    = (const float*)d_in[1];
    const float* b     = (const float*)d_in[2];
    const float* gamma = (const float*)d_in[3];
    const float* beta  = (const float*)d_in[4];
    float* out = (float*)d_out;

    int N = in_sizes[0] / (TT * CC);

    zero_stats_kernel<<<1, 64>>>();
    stats_kernel<<<296, 256>>>(vox, N);
    finalize_kernel<<<1, 64>>>(Wm, b, gamma, beta, N);
    main_kernel<<<N, 64>>>(vox, out);
}